// round 14
// baseline (speedup 1.0000x reference)
#include <cuda_runtime.h>
#include <cuda_bf16.h>
#include <cstdint>
#include <cstring>

// ---------------- Problem constants ----------------
#define NF      128      // NUM_FEATURES
#define NR      6        // NUM_RADIAL
#define TILE_E  64       // edges per CTA (= GEMM M)
#define KC      128      // K per chunk (chunk 0 = x1, 1 = x2, 2 = rbf_h)
#define NCHUNK  3        // 384 / 128
#define NTH     256
#define PK      136      // padded smem row stride in bf16 (272 B) -> conflict-free ldmatrix

// ---------------- smem layout (bytes), single-buffered ----------------
#define ABYTES   (TILE_E * PK * 2)       // 17408
#define BBYTES   (128 * PK * 2)          // 34816
#define SM_AHI   0
#define SM_ALO   (SM_AHI + ABYTES)       // 17408
#define SM_BHI   (SM_ALO + ABYTES)       // 34816
#define SM_BLO   (SM_BHI + BBYTES)       // 69632
#define SM_ZI    (SM_BLO + BBYTES)       // 104448, int[64]
#define SM_ZJ    (SM_ZI + 256)
#define SM_RBF   (SM_ZJ + 256)           // float[64*6] = 1536
#define SM_BYTES (SM_RBF + 1536)         // 106496 B -> 2 CTAs/SM

// W split + transpose, produced by prep kernel: [chunk][n=128][kk=128] bf16
__device__ __align__(16) __nv_bfloat16 g_WT_hi[NCHUNK * 128 * KC];
__device__ __align__(16) __nv_bfloat16 g_WT_lo[NCHUNK * 128 * KC];

// ---------------- helpers ----------------
__device__ __forceinline__ uint32_t smem_u32(const void* p) {
    uint32_t a;
    asm("{ .reg .u64 t; cvta.to.shared.u64 t, %1; cvt.u32.u64 %0, t; }"
        : "=r"(a) : "l"(p));
    return a;
}

__device__ __forceinline__ float swishf(float x) {
    return __fdividef(x, 1.0f + __expf(-x));
}

__device__ __forceinline__ void cp16(uint32_t dst, const void* src) {
    asm volatile("cp.async.cg.shared.global [%0], [%1], 16;"
                 :: "r"(dst), "l"(src) : "memory");
}

__device__ __forceinline__ void ldsm4(uint32_t addr, uint32_t& r0, uint32_t& r1,
                                      uint32_t& r2, uint32_t& r3) {
    asm volatile("ldmatrix.sync.aligned.m8n8.x4.shared.b16 {%0,%1,%2,%3}, [%4];"
                 : "=r"(r0), "=r"(r1), "=r"(r2), "=r"(r3) : "r"(addr));
}

__device__ __forceinline__ void mma_bf16(float* c, uint32_t a0, uint32_t a1,
                                         uint32_t a2, uint32_t a3,
                                         uint32_t b0, uint32_t b1) {
    asm volatile(
        "mma.sync.aligned.m16n8k16.row.col.f32.bf16.bf16.f32 "
        "{%0,%1,%2,%3}, {%4,%5,%6,%7}, {%8,%9}, {%0,%1,%2,%3};"
        : "+f"(c[0]), "+f"(c[1]), "+f"(c[2]), "+f"(c[3])
        : "r"(a0), "r"(a1), "r"(a2), "r"(a3), "r"(b0), "r"(b1));
}

// Split 4 fp32 -> bf16 hi/lo pairs; store 8B each into padded-stride tiles.
__device__ __forceinline__ void store_split(float4 v, char* hi, char* lo, int bo) {
    __nv_bfloat162 h0 = __float22bfloat162_rn(make_float2(v.x, v.y));
    __nv_bfloat162 h1 = __float22bfloat162_rn(make_float2(v.z, v.w));
    float2 f0 = __bfloat1622float2(h0);
    float2 f1 = __bfloat1622float2(h1);
    __nv_bfloat162 l0 = __float22bfloat162_rn(make_float2(v.x - f0.x, v.y - f0.y));
    __nv_bfloat162 l1 = __float22bfloat162_rn(make_float2(v.z - f1.x, v.w - f1.y));
    uint2 hp, lp;
    memcpy(&hp.x, &h0, 4); memcpy(&hp.y, &h1, 4);
    memcpy(&lp.x, &l0, 4); memcpy(&lp.y, &l1, 4);
    *(uint2*)(hi + bo) = hp;
    *(uint2*)(lo + bo) = lp;
}

// ---------------- Prep: W[384,128] -> WT hi/lo [chunk][n][kk] ----------------
__global__ void prep_w_kernel(const float* __restrict__ W) {
    int idx = blockIdx.x * blockDim.x + threadIdx.x;   // [c][n][kk], kk fastest
    if (idx >= NCHUNK * 128 * KC) return;
    int kk = idx & (KC - 1);
    int n  = (idx >> 7) & 127;
    int c  = idx >> 14;
    float v = W[(c * KC + kk) * NF + n];
    __nv_bfloat16 h = __float2bfloat16(v);
    float l = v - __bfloat162float(h);
    g_WT_hi[idx] = h;
    g_WT_lo[idx] = __float2bfloat16(l);
}

// ---------------- Main kernel ----------------
__global__ void __launch_bounds__(NTH, 2)
embedding_block_mma(const int* __restrict__ Z,
                    const float* __restrict__ rbf,
                    const int* __restrict__ idnb_i,
                    const int* __restrict__ idnb_j,
                    const float* __restrict__ emb,
                    const float* __restrict__ W_rbf,
                    const float* __restrict__ b_rbf,
                    const float* __restrict__ bias,
                    float* __restrict__ out,
                    int E) {
    extern __shared__ char smem[];
    const uint32_t sbase = smem_u32(smem);
    const int tid  = threadIdx.x;
    const int lane = tid & 31;
    const int wid  = tid >> 5;
    const int wm   = wid & 1;          // warp M position: rows wm*32 .. +31
    const int wn   = wid >> 1;         // warp N position: cols wn*32 .. +31
    const int base = blockIdx.x * TILE_E;

    int*   zi_s  = (int*)(smem + SM_ZI);
    int*   zj_s  = (int*)(smem + SM_ZJ);
    float* rbf_s = (float*)(smem + SM_RBF);

    // ---- stage per-edge scalars ----
    if (tid < TILE_E) {
        int eg = base + tid;
        int ec = (eg < E) ? eg : (E - 1);
        zi_s[tid] = Z[idnb_i[ec]];
        zj_s[tid] = Z[idnb_j[ec]];
        #pragma unroll
        for (int r = 0; r < NR; r++)
            rbf_s[tid * NR + r] = rbf[(size_t)ec * NR + r];
    }
    __syncthreads();

    // ---- build ids ----
    // A: thread handles row be (0..63), 32-float k quarter kq
    const int be  = tid >> 2;
    const int kq  = (tid & 3) * 32;
    const int abo = be * (PK * 2);
    // B: thread handles row bn (0..127), 128-byte half of the 256B k-row
    const int bn    = tid >> 1;
    const int bhalf = (tid & 1) * 128;
    const uint32_t bdsth = sbase + SM_BHI + bn * (PK * 2) + bhalf;
    const uint32_t bdstl = sbase + SM_BLO + bn * (PK * 2) + bhalf;

    // ---- ldmatrix address components ----
    const int a_row = wm * 32 + (lane & 15);
    const int a_kad = (lane & 16) >> 1;
    const int b_row = wn * 32 + (lane & 7) + ((lane & 16) >> 1);
    const int b_kad = lane & 8;
    const uint32_t ahi_b = sbase + SM_AHI, alo_b = sbase + SM_ALO;
    const uint32_t bhi_b = sbase + SM_BHI, blo_b = sbase + SM_BLO;

    // accumulators: [mi 2][ni 4][4] = 32 regs
    float acc[2][4][4];
    #pragma unroll
    for (int mi = 0; mi < 2; mi++)
        #pragma unroll
        for (int ni = 0; ni < 4; ni++)
            #pragma unroll
            for (int q = 0; q < 4; q++) acc[mi][ni][q] = 0.0f;

    for (int c = 0; c < NCHUNK; c++) {
        if (c > 0) __syncthreads();     // previous chunk fully consumed

        // ---- B chunk via cp.async (pre-split W^T, L2-resident): 256B/thread/term
        {
            const char* sh = (const char*)(g_WT_hi + ((size_t)c * 128 + bn) * KC) + bhalf;
            const char* sl = (const char*)(g_WT_lo + ((size_t)c * 128 + bn) * KC) + bhalf;
            #pragma unroll
            for (int g = 0; g < 8; g++) {
                cp16(bdsth + g * 16, sh + g * 16);
                cp16(bdstl + g * 16, sl + g * 16);
            }
            asm volatile("cp.async.commit_group;" ::: "memory");
        }

        // ---- build A chunk (32 floats/thread): c=0 -> x1, c=1 -> x2, c=2 -> rbf_h
        char* ahi = smem + SM_AHI;
        char* alo = smem + SM_ALO;
        if (c < 2) {
            int zcol = (c == 0) ? zi_s[be] : zj_s[be];
            const float* src = emb + zcol * NF + kq;
            #pragma unroll
            for (int g = 0; g < 8; g++) {
                float4 v = *(const float4*)(src + g * 4);
                store_split(v, ahi, alo, abo + (kq + g * 4) * 2);
            }
        } else {
            float rr[NR];
            #pragma unroll
            for (int r = 0; r < NR; r++) rr[r] = rbf_s[be * NR + r];
            #pragma unroll
            for (int g = 0; g < 8; g++) {
                int f = kq + g * 4;
                float4 a4 = *(const float4*)(b_rbf + f);
                #pragma unroll
                for (int r = 0; r < NR; r++) {
                    float4 w = *(const float4*)(W_rbf + r * NF + f);
                    a4.x = fmaf(rr[r], w.x, a4.x);
                    a4.y = fmaf(rr[r], w.y, a4.y);
                    a4.z = fmaf(rr[r], w.z, a4.z);
                    a4.w = fmaf(rr[r], w.w, a4.w);
                }
                a4.x = swishf(a4.x); a4.y = swishf(a4.y);
                a4.z = swishf(a4.z); a4.w = swishf(a4.w);
                store_split(a4, ahi, alo, abo + (kq + g * 4) * 2);
            }
        }

        asm volatile("cp.async.wait_group 0;" ::: "memory");
        __syncthreads();

        // ---- MMA: 8 k16-steps x (hi.hi + hi.lo + lo.hi) ----
        #pragma unroll
        for (int ks = 0; ks < 8; ks++) {
            const int k0 = ks * 16;
            const uint32_t a_off = (uint32_t)((a_row * PK + k0 + a_kad) * 2);

            uint32_t ah[2][4], al[2][4];
            ldsm4(ahi_b + a_off,               ah[0][0], ah[0][1], ah[0][2], ah[0][3]);
            ldsm4(ahi_b + a_off + 16 * PK * 2, ah[1][0], ah[1][1], ah[1][2], ah[1][3]);
            ldsm4(alo_b + a_off,               al[0][0], al[0][1], al[0][2], al[0][3]);
            ldsm4(alo_b + a_off + 16 * PK * 2, al[1][0], al[1][1], al[1][2], al[1][3]);

            uint32_t bh[4][2], bl[4][2];
            #pragma unroll
            for (int nb = 0; nb < 2; nb++) {
                const uint32_t b_off =
                    (uint32_t)(((b_row + nb * 16) * PK + k0 + b_kad) * 2);
                ldsm4(bhi_b + b_off, bh[2 * nb][0], bh[2 * nb][1],
                                     bh[2 * nb + 1][0], bh[2 * nb + 1][1]);
                ldsm4(blo_b + b_off, bl[2 * nb][0], bl[2 * nb][1],
                                     bl[2 * nb + 1][0], bl[2 * nb + 1][1]);
            }

            #pragma unroll
            for (int mi = 0; mi < 2; mi++)
                #pragma unroll
                for (int ni = 0; ni < 4; ni++) {
                    mma_bf16(acc[mi][ni], ah[mi][0], ah[mi][1], ah[mi][2], ah[mi][3],
                             bh[ni][0], bh[ni][1]);
                    mma_bf16(acc[mi][ni], ah[mi][0], ah[mi][1], ah[mi][2], ah[mi][3],
                             bl[ni][0], bl[ni][1]);
                    mma_bf16(acc[mi][ni], al[mi][0], al[mi][1], al[mi][2], al[mi][3],
                             bh[ni][0], bh[ni][1]);
                }
        }
    }

    // ---- epilogue: +bias, swish, float2 stores ----
    const int r0 = wm * 32 + (lane >> 2);
    const int cbase = wn * 32 + (lane & 3) * 2;

    #pragma unroll
    for (int mi = 0; mi < 2; mi++) {
        const int rowA = base + r0 + mi * 16;
        const int rowB = rowA + 8;
        #pragma unroll
        for (int ni = 0; ni < 4; ni++) {
            const int col = cbase + ni * 8;
            float2 bv = *(const float2*)(bias + col);
            if (rowA < E) {
                float2 o;
                o.x = swishf(acc[mi][ni][0] + bv.x);
                o.y = swishf(acc[mi][ni][1] + bv.y);
                *(float2*)(out + (size_t)rowA * NF + col) = o;
            }
            if (rowB < E) {
                float2 o;
                o.x = swishf(acc[mi][ni][2] + bv.x);
                o.y = swishf(acc[mi][ni][3] + bv.y);
                *(float2*)(out + (size_t)rowB * NF + col) = o;
            }
        }
    }
}

extern "C" void kernel_launch(void* const* d_in, const int* in_sizes, int n_in,
                              void* d_out, int out_size) {
    const int*   Z      = (const int*)  d_in[0];
    const float* rbf    = (const float*)d_in[1];
    const int*   idnb_i = (const int*)  d_in[2];
    const int*   idnb_j = (const int*)  d_in[3];
    const float* emb    = (const float*)d_in[4];
    const float* W_rbf  = (const float*)d_in[5];
    const float* b_rbf  = (const float*)d_in[6];
    const float* W      = (const float*)d_in[7];
    const float* bias   = (const float*)d_in[8];
    float* out = (float*)d_out;

    const int E = in_sizes[2];

    // 1) split + transpose W into bf16 hi/lo chunk layout (runs every call)
    prep_w_kernel<<<(NCHUNK * 128 * KC + 255) / 256, 256>>>(W);

    // 2) fused gather + bf16-split mma.sync GEMM + swish; 2 CTAs/SM, 3 big chunks
    cudaFuncSetAttribute(embedding_block_mma,
                         cudaFuncAttributeMaxDynamicSharedMemorySize, SM_BYTES);
    const int grid = (E + TILE_E - 1) / TILE_E;
    embedding_block_mma<<<grid, NTH, SM_BYTES>>>(
        Z, rbf, idnb_i, idnb_j, emb, W_rbf, b_rbf, bias, out, E);
}

// round 15
// speedup vs baseline: 1.4478x; 1.4478x over previous
#include <cuda_runtime.h>
#include <cuda_fp16.h>
#include <cstdint>
#include <cstring>

// ---------------- Problem constants ----------------
#define NF      128      // NUM_FEATURES
#define NR      6        // NUM_RADIAL
#define TILE_E  64       // edges per CTA (= GEMM M)
#define KC      64       // K per chunk
#define NCHUNK  6        // 384 / 64
#define NTH     256
#define PK      72       // padded smem row stride in fp16 (144 B) -> conflict-free ldmatrix

// ---------------- smem layout (bytes), single-buffered ----------------
// A tile: 64 rows x PK fp16 (rounded h);  B tiles: 128 rows x PK fp16 (hi, lo)
#define SM_A     0                       // 64*PK*2  = 9216
#define SM_BHI   9216                    // 128*PK*2 = 18432
#define SM_BLO   27648
#define SM_ZI    46080                   // int[64]
#define SM_ZJ    46336                   // int[64]
#define SM_RBF   46592                   // float[64*6] = 1536
#define SM_BYTES 48128                   // 47 KB -> 2 CTAs/SM (regs limit anyway)

// W split + transpose, produced by prep kernel: [chunk][n=128][kk=64] fp16
__device__ __align__(16) __half g_WT_hi[NCHUNK * 128 * KC];
__device__ __align__(16) __half g_WT_lo[NCHUNK * 128 * KC];

// ---------------- helpers ----------------
__device__ __forceinline__ uint32_t smem_u32(const void* p) {
    uint32_t a;
    asm("{ .reg .u64 t; cvta.to.shared.u64 t, %1; cvt.u32.u64 %0, t; }"
        : "=r"(a) : "l"(p));
    return a;
}

__device__ __forceinline__ float swishf(float x) {
    return __fdividef(x, 1.0f + __expf(-x));
}

__device__ __forceinline__ void cp16(uint32_t dst, const void* src) {
    asm volatile("cp.async.cg.shared.global [%0], [%1], 16;"
                 :: "r"(dst), "l"(src) : "memory");
}

__device__ __forceinline__ void ldsm4(uint32_t addr, uint32_t& r0, uint32_t& r1,
                                      uint32_t& r2, uint32_t& r3) {
    asm volatile("ldmatrix.sync.aligned.m8n8.x4.shared.b16 {%0,%1,%2,%3}, [%4];"
                 : "=r"(r0), "=r"(r1), "=r"(r2), "=r"(r3) : "r"(addr));
}

__device__ __forceinline__ void mma_f16(float* c, uint32_t a0, uint32_t a1,
                                        uint32_t a2, uint32_t a3,
                                        uint32_t b0, uint32_t b1) {
    asm volatile(
        "mma.sync.aligned.m16n8k16.row.col.f32.f16.f16.f32 "
        "{%0,%1,%2,%3}, {%4,%5,%6,%7}, {%8,%9}, {%0,%1,%2,%3};"
        : "+f"(c[0]), "+f"(c[1]), "+f"(c[2]), "+f"(c[3])
        : "r"(a0), "r"(a1), "r"(a2), "r"(a3), "r"(b0), "r"(b1));
}

// Pack 8 fp32 -> 8 fp16 (rounded) as a uint4.
__device__ __forceinline__ uint4 pack8_f16(float4 v0, float4 v1) {
    __half2 h0 = __floats2half2_rn(v0.x, v0.y);
    __half2 h1 = __floats2half2_rn(v0.z, v0.w);
    __half2 h2 = __floats2half2_rn(v1.x, v1.y);
    __half2 h3 = __floats2half2_rn(v1.z, v1.w);
    uint4 p;
    memcpy(&p.x, &h0, 4); memcpy(&p.y, &h1, 4);
    memcpy(&p.z, &h2, 4); memcpy(&p.w, &h3, 4);
    return p;
}

// ---------------- Prep: W[384,128] -> WT fp16 hi/lo [chunk][n][kk] ----------------
__global__ void prep_w_kernel(const float* __restrict__ W) {
    int idx = blockIdx.x * blockDim.x + threadIdx.x;   // [c][n][kk], kk fastest
    if (idx >= NCHUNK * 128 * KC) return;
    int kk = idx & (KC - 1);
    int n  = (idx >> 6) & 127;
    int c  = idx >> 13;
    float v = W[(c * KC + kk) * NF + n];
    __half h = __float2half_rn(v);
    float l = v - __half2float(h);
    g_WT_hi[idx] = h;
    g_WT_lo[idx] = __float2half_rn(l);
}

// ---------------- Main kernel ----------------
__global__ void __launch_bounds__(NTH, 2)
embedding_block_mma(const int* __restrict__ Z,
                    const float* __restrict__ rbf,
                    const int* __restrict__ idnb_i,
                    const int* __restrict__ idnb_j,
                    const float* __restrict__ emb,
                    const float* __restrict__ W_rbf,
                    const float* __restrict__ b_rbf,
                    const float* __restrict__ bias,
                    float* __restrict__ out,
                    int E) {
    extern __shared__ char smem[];
    const uint32_t sbase = smem_u32(smem);
    const int tid  = threadIdx.x;
    const int lane = tid & 31;
    const int wid  = tid >> 5;
    const int wm   = wid & 1;          // warp M position: rows wm*32 .. +31
    const int wn   = wid >> 1;         // warp N position: cols wn*32 .. +31
    const int base = blockIdx.x * TILE_E;

    int*   zi_s  = (int*)(smem + SM_ZI);
    int*   zj_s  = (int*)(smem + SM_ZJ);
    float* rbf_s = (float*)(smem + SM_RBF);

    // ---- stage per-edge scalars ----
    if (tid < TILE_E) {
        int eg = base + tid;
        int ec = (eg < E) ? eg : (E - 1);
        zi_s[tid] = Z[idnb_i[ec]];
        zj_s[tid] = Z[idnb_j[ec]];
        #pragma unroll
        for (int r = 0; r < NR; r++)
            rbf_s[tid * NR + r] = rbf[(size_t)ec * NR + r];
    }
    __syncthreads();

    // ---- build ids ----
    // A: thread handles row be (0..63), k quarter kq (16 floats -> 16 fp16)
    const int be  = tid >> 2;
    const int kq  = (tid & 3) * 16;
    const int abo = be * (PK * 2);
    // B: thread handles row bn (0..127), byte-half of the 128B k-row
    const int bn    = tid >> 1;
    const int bhalf = (tid & 1) * 64;
    const uint32_t bdsth = sbase + SM_BHI + bn * (PK * 2) + bhalf;
    const uint32_t bdstl = sbase + SM_BLO + bn * (PK * 2) + bhalf;

    // ---- ldmatrix address components ----
    const int a_row = wm * 32 + (lane & 15);
    const int a_kad = (lane & 16) >> 1;
    const int b_row = wn * 32 + (lane & 7) + ((lane & 16) >> 1);
    const int b_kad = lane & 8;
    const uint32_t a_b   = sbase + SM_A;
    const uint32_t bhi_b = sbase + SM_BHI, blo_b = sbase + SM_BLO;

    // accumulators: [mi 2][ni 4][4] = 32 regs
    float acc[2][4][4];
    #pragma unroll
    for (int mi = 0; mi < 2; mi++)
        #pragma unroll
        for (int ni = 0; ni < 4; ni++)
            #pragma unroll
            for (int q = 0; q < 4; q++) acc[mi][ni][q] = 0.0f;

    for (int c = 0; c < NCHUNK; c++) {
        if (c > 0) __syncthreads();     // previous chunk fully consumed

        // ---- B chunk via cp.async (pre-split W^T, L2-resident) ----
        {
            const char* sh = (const char*)(g_WT_hi + ((size_t)c * 128 + bn) * KC) + bhalf;
            const char* sl = (const char*)(g_WT_lo + ((size_t)c * 128 + bn) * KC) + bhalf;
            #pragma unroll
            for (int g = 0; g < 4; g++) {
                cp16(bdsth + g * 16, sh + g * 16);
                cp16(bdstl + g * 16, sl + g * 16);
            }
            asm volatile("cp.async.commit_group;" ::: "memory");
        }

        // ---- build A chunk: h[e][64c .. 64c+64) rounded to fp16 ----
        char* a_s = smem + SM_A;
        if (c < 4) {
            int zcol = (c < 2) ? zi_s[be] : zj_s[be];
            const float* src = emb + zcol * NF + (c & 1) * 64 + kq;
            float4 v0 = *(const float4*)(src);
            float4 v1 = *(const float4*)(src + 4);
            float4 v2 = *(const float4*)(src + 8);
            float4 v3 = *(const float4*)(src + 12);
            *(uint4*)(a_s + abo + kq * 2)      = pack8_f16(v0, v1);
            *(uint4*)(a_s + abo + kq * 2 + 16) = pack8_f16(v2, v3);
        } else {
            const int fbase = (c - 4) * 64 + kq;
            float rr[NR];
            #pragma unroll
            for (int r = 0; r < NR; r++) rr[r] = rbf_s[be * NR + r];
            float4 o[4];
            #pragma unroll
            for (int g = 0; g < 4; g++) {
                int f = fbase + g * 4;
                float4 a4 = *(const float4*)(b_rbf + f);
                #pragma unroll
                for (int r = 0; r < NR; r++) {
                    float4 w = *(const float4*)(W_rbf + r * NF + f);
                    a4.x = fmaf(rr[r], w.x, a4.x);
                    a4.y = fmaf(rr[r], w.y, a4.y);
                    a4.z = fmaf(rr[r], w.z, a4.z);
                    a4.w = fmaf(rr[r], w.w, a4.w);
                }
                a4.x = swishf(a4.x); a4.y = swishf(a4.y);
                a4.z = swishf(a4.z); a4.w = swishf(a4.w);
                o[g] = a4;
            }
            *(uint4*)(a_s + abo + kq * 2)      = pack8_f16(o[0], o[1]);
            *(uint4*)(a_s + abo + kq * 2 + 16) = pack8_f16(o[2], o[3]);
        }

        asm volatile("cp.async.wait_group 0;" ::: "memory");
        __syncthreads();

        // ---- MMA: 4 k16-steps x (a.bhi + a.blo) ----
        #pragma unroll
        for (int ks = 0; ks < 4; ks++) {
            const int k0 = ks * 16;
            const uint32_t a_off = (uint32_t)((a_row * PK + k0 + a_kad) * 2);

            uint32_t ah[2][4];
            ldsm4(a_b + a_off,               ah[0][0], ah[0][1], ah[0][2], ah[0][3]);
            ldsm4(a_b + a_off + 16 * PK * 2, ah[1][0], ah[1][1], ah[1][2], ah[1][3]);

            uint32_t bh[4][2], bl[4][2];
            #pragma unroll
            for (int nb = 0; nb < 2; nb++) {
                const uint32_t b_off =
                    (uint32_t)(((b_row + nb * 16) * PK + k0 + b_kad) * 2);
                ldsm4(bhi_b + b_off, bh[2 * nb][0], bh[2 * nb][1],
                                     bh[2 * nb + 1][0], bh[2 * nb + 1][1]);
                ldsm4(blo_b + b_off, bl[2 * nb][0], bl[2 * nb][1],
                                     bl[2 * nb + 1][0], bl[2 * nb + 1][1]);
            }

            #pragma unroll
            for (int mi = 0; mi < 2; mi++)
                #pragma unroll
                for (int ni = 0; ni < 4; ni++) {
                    mma_f16(acc[mi][ni], ah[mi][0], ah[mi][1], ah[mi][2], ah[mi][3],
                            bh[ni][0], bh[ni][1]);
                    mma_f16(acc[mi][ni], ah[mi][0], ah[mi][1], ah[mi][2], ah[mi][3],
                            bl[ni][0], bl[ni][1]);
                }
        }
    }

    // ---- epilogue: +bias, swish, float2 stores ----
    const int r0 = wm * 32 + (lane >> 2);
    const int cbase = wn * 32 + (lane & 3) * 2;

    #pragma unroll
    for (int mi = 0; mi < 2; mi++) {
        const int rowA = base + r0 + mi * 16;
        const int rowB = rowA + 8;
        #pragma unroll
        for (int ni = 0; ni < 4; ni++) {
            const int col = cbase + ni * 8;
            float2 bv = *(const float2*)(bias + col);
            if (rowA < E) {
                float2 o;
                o.x = swishf(acc[mi][ni][0] + bv.x);
                o.y = swishf(acc[mi][ni][1] + bv.y);
                *(float2*)(out + (size_t)rowA * NF + col) = o;
            }
            if (rowB < E) {
                float2 o;
                o.x = swishf(acc[mi][ni][2] + bv.x);
                o.y = swishf(acc[mi][ni][3] + bv.y);
                *(float2*)(out + (size_t)rowB * NF + col) = o;
            }
        }
    }
}

extern "C" void kernel_launch(void* const* d_in, const int* in_sizes, int n_in,
                              void* d_out, int out_size) {
    const int*   Z      = (const int*)  d_in[0];
    const float* rbf    = (const float*)d_in[1];
    const int*   idnb_i = (const int*)  d_in[2];
    const int*   idnb_j = (const int*)  d_in[3];
    const float* emb    = (const float*)d_in[4];
    const float* W_rbf  = (const float*)d_in[5];
    const float* b_rbf  = (const float*)d_in[6];
    const float* W      = (const float*)d_in[7];
    const float* bias   = (const float*)d_in[8];
    float* out = (float*)d_out;

    const int E = in_sizes[2];

    // 1) split + transpose W into fp16 hi/lo chunk layout (runs every call)
    prep_w_kernel<<<(NCHUNK * 128 * KC + 255) / 256, 256>>>(W);

    // 2) fused gather + 2-term fp16 mma.sync GEMM + swish; 2 CTAs/SM
    cudaFuncSetAttribute(embedding_block_mma,
                         cudaFuncAttributeMaxDynamicSharedMemorySize, SM_BYTES);
    const int grid = (E + TILE_E - 1) / TILE_E;
    embedding_block_mma<<<grid, NTH, SM_BYTES>>>(
        Z, rbf, idnb_i, idnb_j, emb, W_rbf, b_rbf, bias, out, E);
}